// round 17
// baseline (speedup 1.0000x reference)
#include <cuda_runtime.h>
#include <cuda_fp16.h>
#include <cstdint>

#define NB 8
#define NTX 128
#define NTY 128
#define ND 512
#define NH 512
#define TYB 8

// Scratch (allocation-free rule: __device__ globals)
// T = tanh(proj), V = Va * tanh(proj)   (f32, transposed [b][h][t])
__device__ float g_TW[NB * NH * NTX];
__device__ float g_VW[NB * NH * NTX];
__device__ float g_TU[NB * NH * NTY];
__device__ float g_VU[NB * NH * NTY];

__device__ __forceinline__ void mma_f16(float d[4], const uint32_t a[4],
                                        const uint32_t b[2]) {
    asm volatile(
        "mma.sync.aligned.m16n8k16.row.col.f32.f16.f16.f32 "
        "{%0,%1,%2,%3}, {%4,%5,%6,%7}, {%8,%9}, {%0,%1,%2,%3};"
        : "+f"(d[0]), "+f"(d[1]), "+f"(d[2]), "+f"(d[3])
        : "r"(a[0]), "r"(a[1]), "r"(a[2]), "r"(a[3]), "r"(b[0]), "r"(b[1]));
}

__device__ __forceinline__ float tanh_f32(float x) {
    float y;
    asm("tanh.approx.f32 %0, %1;" : "=f"(y) : "f"(x));
    return y;
}

__device__ __forceinline__ float rcp_f32(float x) {
    float y;
    asm("rcp.approx.f32 %0, %1;" : "=f"(y) : "f"(x));
    return y;
}

// ---------------------------------------------------------------------------
// Kernel 1 (fp16 HMMA, double-buffered smem, R16 mainloop): proj = A@W+bias;
// epilogue writes T = tanh(proj), V = Va*T (f32, [h][t] transposed).
// ---------------------------------------------------------------------------
__global__ void __launch_bounds__(256)
bahdanau_gemm_tc(const float* __restrict__ Ctx, const float* __restrict__ X,
                 const float* __restrict__ Wa, const float* __restrict__ bWa,
                 const float* __restrict__ Ua, const float* __restrict__ bUa,
                 const float* __restrict__ Va)
{
    const int which = blockIdx.z >> 3;       // 0: Wc, 1: Ux
    const int b     = blockIdx.z & 7;
    const float* A    = (which ? X  : Ctx) + b * NTX * ND;   // [128][512]
    const float* W    =  which ? Ua : Wa;                    // [512][512]
    const float* bias =  which ? bUa : bWa;
    float* Tout = (which ? g_TU : g_TW) + (size_t)b * NH * NTX;  // [512][128]
    float* Vout = (which ? g_VU : g_VW) + (size_t)b * NH * NTX;

    const int h0 = blockIdx.x * 64;
    const int t0 = blockIdx.y * 64;

    // smem: As[2] 64x40 halfs (2x5120 B), Bs[2] 64x34 halfs (2x4352 B) = 18944 B
    // Sout [64][68] f32 (17408 B) overlays after the mainloop.
    __shared__ __align__(16) char smem_raw[18944];
    __half* AsBuf = reinterpret_cast<__half*>(smem_raw);            // + buf*2560
    __half* BsBuf = reinterpret_cast<__half*>(smem_raw + 10240);    // + buf*2176
    float (*Sout)[68] = reinterpret_cast<float(*)[68]>(smem_raw);

    const int tid  = threadIdx.x;
    const int warp = tid >> 5, lane = tid & 31;
    const int wm = warp >> 2, wn = warp & 3;    // 2x4 warp grid
    const int gid = lane >> 2, tq = lane & 3;

    const int arow = tid >> 2, ak = (tid & 3) * 8;   // A: 64 t-rows x 32 k
    const int brow = tid >> 3, bh = (tid & 7) * 8;   // B: 32 k-rows x 64 h

    const float* Abase = A + (t0 + arow) * ND + ak;
    const float* Bbase = W + brow * NH + h0 + bh;

    float4 pa[2], pb[2];
#pragma unroll
    for (int i = 0; i < 2; i++) pa[i] = *(const float4*)(Abase + i * 4);
#pragma unroll
    for (int i = 0; i < 2; i++) pb[i] = *(const float4*)(Bbase + i * 4);

    {   // STS chunk 0 -> buffer 0
        __half2 h2[4];
        h2[0] = __floats2half2_rn(pa[0].x, pa[0].y);
        h2[1] = __floats2half2_rn(pa[0].z, pa[0].w);
        h2[2] = __floats2half2_rn(pa[1].x, pa[1].y);
        h2[3] = __floats2half2_rn(pa[1].z, pa[1].w);
        *reinterpret_cast<uint4*>(AsBuf + arow * 40 + ak) =
            *reinterpret_cast<uint4*>(h2);
        const float* pf = reinterpret_cast<const float*>(pb);
#pragma unroll
        for (int i = 0; i < 8; i++)
            BsBuf[(bh + i) * 34 + brow] = __float2half_rn(pf[i]);
    }
#pragma unroll
    for (int i = 0; i < 2; i++) pa[i] = *(const float4*)(Abase + 32 + i * 4);
#pragma unroll
    for (int i = 0; i < 2; i++) pb[i] = *(const float4*)(Bbase + (size_t)32 * NH + i * 4);

    float acc[2][2][4];
#pragma unroll
    for (int mt = 0; mt < 2; mt++)
#pragma unroll
        for (int nt = 0; nt < 2; nt++)
#pragma unroll
            for (int r = 0; r < 4; r++) acc[mt][nt][r] = 0.f;

#pragma unroll 1
    for (int kc = 0; kc < 16; kc++) {
        __syncthreads();

        if (kc + 1 < 16) {   // STS chunk kc+1 (overlaps mma)
            __half* as = AsBuf + ((kc + 1) & 1) * 2560;
            __half* bs = BsBuf + ((kc + 1) & 1) * 2176;
            __half2 h2[4];
            h2[0] = __floats2half2_rn(pa[0].x, pa[0].y);
            h2[1] = __floats2half2_rn(pa[0].z, pa[0].w);
            h2[2] = __floats2half2_rn(pa[1].x, pa[1].y);
            h2[3] = __floats2half2_rn(pa[1].z, pa[1].w);
            *reinterpret_cast<uint4*>(as + arow * 40 + ak) =
                *reinterpret_cast<uint4*>(h2);
            const float* pf = reinterpret_cast<const float*>(pb);
#pragma unroll
            for (int i = 0; i < 8; i++)
                bs[(bh + i) * 34 + brow] = __float2half_rn(pf[i]);
        }
        if (kc + 2 < 16) {   // prefetch chunk kc+2 regs
            const float* an = Abase + (kc + 2) * 32;
            const float* bn = Bbase + (size_t)(kc + 2) * 32 * NH;
#pragma unroll
            for (int i = 0; i < 2; i++) pa[i] = *(const float4*)(an + i * 4);
#pragma unroll
            for (int i = 0; i < 2; i++) pb[i] = *(const float4*)(bn + i * 4);
        }

        const __half* as = AsBuf + (kc & 1) * 2560;
        const __half* bs = BsBuf + (kc & 1) * 2176;
#pragma unroll
        for (int ks = 0; ks < 2; ks++) {
            const int kb = ks * 16;
            uint32_t af[2][4], bf[2][2];
#pragma unroll
            for (int mt = 0; mt < 2; mt++) {
                const int r = wm * 32 + mt * 16 + gid;
                af[mt][0] = *reinterpret_cast<const uint32_t*>(as + r * 40 + kb + 2 * tq);
                af[mt][1] = *reinterpret_cast<const uint32_t*>(as + (r + 8) * 40 + kb + 2 * tq);
                af[mt][2] = *reinterpret_cast<const uint32_t*>(as + r * 40 + kb + 2 * tq + 8);
                af[mt][3] = *reinterpret_cast<const uint32_t*>(as + (r + 8) * 40 + kb + 2 * tq + 8);
            }
#pragma unroll
            for (int nt = 0; nt < 2; nt++) {
                const int c = wn * 16 + nt * 8 + gid;
                bf[nt][0] = *reinterpret_cast<const uint32_t*>(bs + c * 34 + kb + 2 * tq);
                bf[nt][1] = *reinterpret_cast<const uint32_t*>(bs + c * 34 + kb + 2 * tq + 8);
            }
#pragma unroll
            for (int mt = 0; mt < 2; mt++)
#pragma unroll
                for (int nt = 0; nt < 2; nt++)
                    mma_f16(acc[mt][nt], af[mt], bf[nt]);
        }
    }
    __syncthreads();

    // Transpose via smem: Sout[n(h)][m(t)]
#pragma unroll
    for (int mt = 0; mt < 2; mt++)
#pragma unroll
        for (int nt = 0; nt < 2; nt++) {
            const int n = wn * 16 + nt * 8 + 2 * tq;
            const int m = wm * 32 + mt * 16 + gid;
            Sout[n    ][m    ] = acc[mt][nt][0];
            Sout[n + 1][m    ] = acc[mt][nt][1];
            Sout[n    ][m + 8] = acc[mt][nt][2];
            Sout[n + 1][m + 8] = acc[mt][nt][3];
        }
    __syncthreads();

    // Epilogue: bias + tanh -> T, Va*T -> V. 64 h-rows x 64 t; 16 t/thread.
    {
        const int row = tid >> 2;
        const int cg  = (tid & 3) * 16;
        const float bv = __ldg(&bias[h0 + row]);
        const float va = __ldg(&Va[h0 + row]);
        float tv[16], vv[16];
#pragma unroll
        for (int k = 0; k < 16; k++) {
            float t = tanh_f32(Sout[row][cg + k] + bv);
            tv[k] = t;
            vv[k] = va * t;
        }
        float* trow = Tout + (size_t)(h0 + row) * NTX + t0 + cg;
        float* vrow = Vout + (size_t)(h0 + row) * NTX + t0 + cg;
#pragma unroll
        for (int k = 0; k < 4; k++) {
            *reinterpret_cast<float4*>(trow + 4 * k) =
                *reinterpret_cast<float4*>(&tv[4 * k]);
            *reinterpret_cast<float4*>(vrow + 4 * k) =
                *reinterpret_cast<float4*>(&vv[4 * k]);
        }
    }
}

// ---------------------------------------------------------------------------
// Kernel 2: fused scores + softmax + cv + LayerNorm + residual.
// Phase 1: tanh addition identity, LEAN form — per element:
//   den = fmaf(tw, tu, 1);  den = max(den, 1e-6);
//   s  += (vw + vu) * rcp(den)
// 1 tx per thread, 8 ty, 4 h-groups x 128 h. MUFU.RCP rt=8 -> 16 us floor.
// ---------------------------------------------------------------------------
__global__ void __launch_bounds__(512)
bahdanau_attn(const float* __restrict__ Ctx, const float* __restrict__ X,
              const float* __restrict__ gamma, const float* __restrict__ beta,
              float* __restrict__ out)
{
    const int b   = blockIdx.x >> 4;
    const int ty0 = (blockIdx.x & 15) * TYB;

    __shared__ __align__(16) float pool[8192];        // 32 KB
    __shared__ __align__(16) float attn_s[TYB][NTX];  //  4 KB
    float* tu_s = pool;          // [512][8] during phase 1
    float* vu_s = pool + 4096;   // [512][8] during phase 1
    // after phase 1: pool[0..4096) = part[4][TYB][NTX]
    // after phase 2: pool[0..8192) = cv [2][TYB][ND]

    const int tid = threadIdx.x;

    // Stage tu/vu (one h per thread: 8 ty f32 = 2 x float4)
    {
        const float* tsrc = g_TU + ((size_t)(b * NH + tid)) * NTY + ty0;
        const float* vsrc = g_VU + ((size_t)(b * NH + tid)) * NTY + ty0;
        *reinterpret_cast<float4*>(&tu_s[tid * 8])     = *(const float4*)(tsrc);
        *reinterpret_cast<float4*>(&tu_s[tid * 8 + 4]) = *(const float4*)(tsrc + 4);
        *reinterpret_cast<float4*>(&vu_s[tid * 8])     = *(const float4*)(vsrc);
        *reinterpret_cast<float4*>(&vu_s[tid * 8 + 4]) = *(const float4*)(vsrc + 4);
    }
    __syncthreads();

    // ---- Phase 1
    {
        const int txi = tid & 127;       // 1 tx per thread
        const int g   = tid >> 7;        // h-group: h in [g*128, g*128+128)

        float sacc[TYB];
#pragma unroll
        for (int j = 0; j < TYB; j++) sacc[j] = 0.f;

        const float* twp = g_TW + (size_t)(b * NH + g * 128) * NTX + txi;
        const float* vwp = g_VW + (size_t)(b * NH + g * 128) * NTX + txi;

        float twr[4], vwr[4];
#pragma unroll
        for (int i = 0; i < 4; i++) {
            twr[i] = __ldg(twp + i * NTX);
            vwr[i] = __ldg(vwp + i * NTX);
        }

#pragma unroll 1
        for (int hh = 0; hh < 128; hh += 4) {
            float twn[4], vwn[4];
            const bool more = (hh + 4) < 128;
#pragma unroll
            for (int i = 0; i < 4; i++) {
                twn[i] = more ? __ldg(twp + (hh + 4 + i) * NTX) : 0.f;
                vwn[i] = more ? __ldg(vwp + (hh + 4 + i) * NTX) : 0.f;
            }

#pragma unroll
            for (int i = 0; i < 4; i++) {
                const int h = g * 128 + hh + i;
                const float tw = twr[i], vw = vwr[i];
                float4 t0 = *reinterpret_cast<const float4*>(&tu_s[h * 8]);
                float4 t1 = *reinterpret_cast<const float4*>(&tu_s[h * 8 + 4]);
                float4 v0 = *reinterpret_cast<const float4*>(&vu_s[h * 8]);
                float4 v1 = *reinterpret_cast<const float4*>(&vu_s[h * 8 + 4]);
                const float* tu = reinterpret_cast<const float*>(&t0);
                const float* tb = reinterpret_cast<const float*>(&t1);
                const float* vu = reinterpret_cast<const float*>(&v0);
                const float* vb = reinterpret_cast<const float*>(&v1);
#pragma unroll
                for (int j = 0; j < 4; j++) {
                    float den = fmaxf(fmaf(tw, tu[j], 1.f), 1e-6f);
                    sacc[j] = fmaf(vw + vu[j], rcp_f32(den), sacc[j]);
                }
#pragma unroll
                for (int j = 0; j < 4; j++) {
                    float den = fmaxf(fmaf(tw, tb[j], 1.f), 1e-6f);
                    sacc[4 + j] = fmaf(vw + vb[j], rcp_f32(den), sacc[4 + j]);
                }
            }
#pragma unroll
            for (int i = 0; i < 4; i++) { twr[i] = twn[i]; vwr[i] = vwn[i]; }
        }

        __syncthreads();   // tu/vu reads done before part overlays pool
#pragma unroll
        for (int j = 0; j < TYB; j++)
            pool[(g * TYB + j) * NTX + txi] = sacc[j];
    }
    __syncthreads();

    // ---- Phase 2: softmax over tx per ty row; warp j (j<8) handles row j.
    if (tid < 256) {
        const int j = tid >> 5, lane = tid & 31;
        float vals[4];
        float mx = -1e30f;
#pragma unroll
        for (int i = 0; i < 4; i++) {
            int t = lane + i * 32;
            float v = pool[(0 * TYB + j) * NTX + t]
                    + pool[(1 * TYB + j) * NTX + t]
                    + pool[(2 * TYB + j) * NTX + t]
                    + pool[(3 * TYB + j) * NTX + t];
            vals[i] = v;
            mx = fmaxf(mx, v);
        }
#pragma unroll
        for (int off = 16; off; off >>= 1)
            mx = fmaxf(mx, __shfl_xor_sync(0xffffffffu, mx, off));
        float sum = 0.f;
#pragma unroll
        for (int i = 0; i < 4; i++) {
            vals[i] = __expf(vals[i] - mx);
            sum += vals[i];
        }
#pragma unroll
        for (int off = 16; off; off >>= 1)
            sum += __shfl_xor_sync(0xffffffffu, sum, off);
        float inv = __frcp_rn(sum);
#pragma unroll
        for (int i = 0; i < 4; i++)
            attn_s[j][lane + i * 32] = vals[i] * inv;
    }
    __syncthreads();

    // ---- Phase 3: cv[j][d] = sum_tx attn[j][tx] * context[b][tx][d]
    {
        const int g2 = tid >> 8;
        const int l  = tid & 255;
        const int d0 = l * 2;
        float acc[TYB][2];
#pragma unroll
        for (int j = 0; j < TYB; j++) { acc[j][0] = 0.f; acc[j][1] = 0.f; }
        const float* cbase = Ctx + (size_t)b * NTX * ND + (size_t)(g2 * 64) * ND + d0;
#pragma unroll 1
        for (int t = 0; t < 64; t += 8) {
            float2 c[8];
#pragma unroll
            for (int i = 0; i < 8; i++)
                c[i] = *reinterpret_cast<const float2*>(cbase + (size_t)(t + i) * ND);
#pragma unroll
            for (int i = 0; i < 8; i++) {
                const int tt = g2 * 64 + t + i;
#pragma unroll
                for (int j = 0; j < TYB; j++) {
                    float a = attn_s[j][tt];
                    acc[j][0] += a * c[i].x;
                    acc[j][1] += a * c[i].y;
                }
            }
        }
        __syncthreads();   // phase-2 partial reads done before cv overlay
#pragma unroll
        for (int j = 0; j < TYB; j++) {
            pool[g2 * 4096 + j * 512 + d0]     = acc[j][0];
            pool[g2 * 4096 + j * 512 + d0 + 1] = acc[j][1];
        }
    }
    __syncthreads();

    // ---- Phase 4: LayerNorm + residual. Warp j (j<8) handles row j.
    if (tid < 256) {
        const int j = tid >> 5, lane = tid & 31;
        float vals[16];
        float sum = 0.f;
#pragma unroll
        for (int i = 0; i < 16; i++) {
            int d = i * 32 + lane;
            vals[i] = pool[j * 512 + d] + pool[4096 + j * 512 + d];
            sum += vals[i];
        }
#pragma unroll
        for (int off = 16; off; off >>= 1)
            sum += __shfl_xor_sync(0xffffffffu, sum, off);
        const float mean = sum * (1.0f / ND);
        float vsum = 0.f;
#pragma unroll
        for (int i = 0; i < 16; i++) {
            float dlt = vals[i] - mean;
            vsum += dlt * dlt;
        }
#pragma unroll
        for (int off = 16; off; off >>= 1)
            vsum += __shfl_xor_sync(0xffffffffu, vsum, off);
        const float scale = rsqrtf(vsum * (1.0f / ND) + 1e-3f);

        const int ty = ty0 + j;
        const float* xr = X + ((size_t)b * NTY + ty) * ND;
        float* orow = out + ((size_t)b * NTY + ty) * ND;
#pragma unroll
        for (int i = 0; i < 16; i++) {
            int d = i * 32 + lane;
            orow[d] = (vals[i] - mean) * scale * gamma[d] + beta[d] + xr[d];
        }
    }
}

// ---------------------------------------------------------------------------
extern "C" void kernel_launch(void* const* d_in, const int* in_sizes, int n_in,
                              void* d_out, int out_size)
{
    const float* ctx   = (const float*)d_in[0];
    const float* x     = (const float*)d_in[1];
    const float* Wa    = (const float*)d_in[2];
    const float* bWa   = (const float*)d_in[3];
    const float* Ua    = (const float*)d_in[4];
    const float* bUa   = (const float*)d_in[5];
    const float* Va    = (const float*)d_in[6];
    // d_in[7] = bVa: scalar added to scores; cancels exactly in softmax.
    const float* gamma = (const float*)d_in[8];
    const float* beta  = (const float*)d_in[9];
    float* out = (float*)d_out;

    dim3 g1(NH / 64, NTX / 64, NB * 2);   // (8, 2, 16) = 256 blocks
    bahdanau_gemm_tc<<<g1, 256>>>(ctx, x, Wa, bWa, Ua, bUa, Va);

    bahdanau_attn<<<NB * (NTY / TYB), 512>>>(ctx, x, gamma, beta, out);
}